// round 14
// baseline (speedup 1.0000x reference)
#include <cuda_runtime.h>
#include <cuda_fp16.h>
#include <cstdint>

// dw[s,t] = SCALE * sum_b nt[b,s] * ap[b,t]
// SCALE = (0.05*0.05 - 0.01*0.05) * 0.001 / 256 = 7.8125e-9
#define S_DIM 8192
#define T_DIM 8192
#define K_DIM 256

static constexpr float SCALE_F = 7.8125e-9f;

static constexpr int THREADS = 128;            // 4 warps, warp tile 64x64
static constexpr int KC      = 64;             // K halves per stage
static constexpr int NCHUNK  = K_DIM / KC;     // 4
static constexpr int PITCHB    = (KC + 8) * 2; // 144 B row pitch (36 words -> banks 4r, conflict-free)
static constexpr int STAGE_OP  = 128 * PITCHB; // 18432 B per operand per stage
static constexpr int STAGE_TOT = 2 * STAGE_OP; // 36864
static constexpr int NSTAGE    = 3;
static constexpr int SMEM_BYTES = NSTAGE * STAGE_TOT;  // 110592 -> 2 CTAs/SM

// fp16 TRANSPOSED copies: g_at[s][k] = nt[k][s], g_bt[t][k] = ap[k][t]
__device__ __half g_at[(size_t)S_DIM * K_DIM];
__device__ __half g_bt[(size_t)T_DIM * K_DIM];

// ---------------- convert + transpose pass: fp32 [k][s] -> fp16 [s][k] ----------------
__global__ void cvt_t_kernel(const float* __restrict__ a, const float* __restrict__ b) {
    __shared__ float tile[64][65];
    const int s0 = blockIdx.x * 64;
    const int k0 = blockIdx.y * 64;
    const float* src = blockIdx.z ? b : a;
    __half* dst = blockIdx.z ? g_bt : g_at;
    const int tid = threadIdx.x;
#pragma unroll
    for (int i = 0; i < 4; i++) {
        int lin = (tid + i * 256) * 4;
        int row = lin >> 6, col = lin & 63;
        float4 v = *(const float4*)(src + (size_t)(k0 + row) * S_DIM + s0 + col);
        tile[row][col] = v.x; tile[row][col + 1] = v.y;
        tile[row][col + 2] = v.z; tile[row][col + 3] = v.w;
    }
    __syncthreads();
#pragma unroll
    for (int i = 0; i < 4; i++) {
        int lin = tid + i * 256;        // 0..1023
        int srow = lin >> 4;            // 0..63
        int kc = (lin & 15) * 4;        // 0..60
        __half h[4];
#pragma unroll
        for (int j = 0; j < 4; j++) h[j] = __float2half_rn(tile[kc + j][srow]);
        *(uint2*)(dst + (size_t)(s0 + srow) * K_DIM + k0 + kc) = *(const uint2*)h;
    }
}

// ---------------- helpers ----------------
__device__ __forceinline__ uint32_t smem_u32(const void* p) {
    uint32_t a;
    asm("{ .reg .u64 t; cvta.to.shared.u64 t, %1; cvt.u32.u64 %0, t; }" : "=r"(a) : "l"(p));
    return a;
}

__device__ __forceinline__ void cp16(uint32_t s, const void* g) {
    asm volatile("cp.async.cg.shared.global [%0], [%1], 16;" :: "r"(s), "l"(g));
}

// NON-transposed ldmatrix: k is contiguous in smem for both operands
__device__ __forceinline__ void ldmx4(uint32_t* d, uint32_t addr) {
    asm volatile("ldmatrix.sync.aligned.m8n8.x4.shared.b16 {%0,%1,%2,%3}, [%4];"
                 : "=r"(d[0]), "=r"(d[1]), "=r"(d[2]), "=r"(d[3]) : "r"(addr));
}

__device__ __forceinline__ void mma16816(float* d, const uint32_t* a, uint32_t b0, uint32_t b1) {
    asm volatile(
        "mma.sync.aligned.m16n8k16.row.col.f32.f16.f16.f32 "
        "{%0,%1,%2,%3}, {%4,%5,%6,%7}, {%8,%9}, {%0,%1,%2,%3};"
        : "+f"(d[0]), "+f"(d[1]), "+f"(d[2]), "+f"(d[3])
        : "r"(a[0]), "r"(a[1]), "r"(a[2]), "r"(a[3]), "r"(b0), "r"(b1));
}

// ---------------- GEMM: out[8192,8192] = SCALE * A(8192x256) B(8192x256)^T ----------------
__global__ __launch_bounds__(THREADS, 2)
void stdp_gemm_kernel(float* __restrict__ out) {
    extern __shared__ __align__(16) char smem[];
    const uint32_t sb = smem_u32(smem);
    const int tid = threadIdx.x;
    const int bm = blockIdx.x;   // M tile (fast dim -> wave shares B tiles in L2)
    const int bn = blockIdx.y;

    const __half* __restrict__ A = g_at;  // [m][k], k contiguous
    const __half* __restrict__ B = g_bt;  // [n][k], k contiguous

    const size_t a_m0 = (size_t)bm * 128;
    const size_t b_n0 = (size_t)bn * 128;

    // cp.async mapping: 128 rows x 8 segs of 16B per operand; 8 chunks/thread/operand
    int rowv[8], segv[8];
#pragma unroll
    for (int i = 0; i < 8; i++) {
        int cc = tid + i * THREADS;
        rowv[i] = cc >> 3;
        segv[i] = cc & 7;
    }

#define LOAD_STAGE(st, k0)                                                          \
    do {                                                                            \
        uint32_t _sbase = sb + (uint32_t)(st) * STAGE_TOT;                          \
        _Pragma("unroll")                                                           \
        for (int i = 0; i < 8; i++) {                                               \
            uint32_t _so = (uint32_t)(rowv[i] * PITCHB + segv[i] * 16);             \
            cp16(_sbase + _so,                                                      \
                 A + (a_m0 + rowv[i]) * K_DIM + (k0) + segv[i] * 8);                \
            cp16(_sbase + STAGE_OP + _so,                                           \
                 B + (b_n0 + rowv[i]) * K_DIM + (k0) + segv[i] * 8);                \
        }                                                                           \
    } while (0)

    LOAD_STAGE(0, 0);
    asm volatile("cp.async.commit_group;" ::: "memory");
    LOAD_STAGE(1, KC);
    asm volatile("cp.async.commit_group;" ::: "memory");

    // ---- warp layout: 4 warps = 2(m) x 2(n); warp tile 64x64 ----
    const int warp = tid >> 5, lane = tid & 31;
    const int wm = warp & 1;        // m offset wm*64
    const int wn = warp >> 1;       // n offset wn*64

    // non-trans ldmatrix lane mapping: row = lane&15, k-half-group = lane>>4
    const int lrow = lane & 15;
    const uint32_t kq = (uint32_t)((lane >> 4) * 16);   // bytes
    const uint32_t a_off = (uint32_t)((wm * 64 + lrow) * PITCHB) + kq;
    const uint32_t b_off = (uint32_t)STAGE_OP + (uint32_t)((wn * 64 + lrow) * PITCHB) + kq;

    float acc[4][8][4];
#pragma unroll
    for (int mi = 0; mi < 4; mi++)
#pragma unroll
        for (int nj = 0; nj < 8; nj++)
#pragma unroll
            for (int q = 0; q < 4; q++) acc[mi][nj][q] = 0.f;

    uint32_t af[2][4][4], bf[2][4][4];   // double-buffered fragments

#pragma unroll 1
    for (int c = 0; c < NCHUNK; c++) {
        asm volatile("cp.async.wait_group 1;" ::: "memory");
        __syncthreads();
        if (c + 2 < NCHUNK) LOAD_STAGE(c + 2 < NSTAGE ? c + 2 : c + 2 - NSTAGE, (c + 2) * KC);
        asm volatile("cp.async.commit_group;" ::: "memory");

        const int st = (c < NSTAGE) ? c : c - NSTAGE;
        const uint32_t stbase = sb + (uint32_t)st * STAGE_TOT;

        // prefetch ks=0 fragments (mi/nb step = 16 rows = 16*PITCHB bytes)
#pragma unroll
        for (int mi = 0; mi < 4; mi++) ldmx4(af[0][mi], stbase + a_off + mi * (16 * PITCHB));
#pragma unroll
        for (int nb = 0; nb < 4; nb++) ldmx4(bf[0][nb], stbase + b_off + nb * (16 * PITCHB));

#pragma unroll
        for (int ks = 0; ks < KC / 16; ks++) {
            const int cur = ks & 1, nxt = cur ^ 1;
            if (ks < KC / 16 - 1) {
                const uint32_t ko = (uint32_t)((ks + 1) * 32);   // 16 halves = 32 B along k
#pragma unroll
                for (int mi = 0; mi < 4; mi++)
                    ldmx4(af[nxt][mi], stbase + a_off + mi * (16 * PITCHB) + ko);
#pragma unroll
                for (int nb = 0; nb < 4; nb++)
                    ldmx4(bf[nxt][nb], stbase + b_off + nb * (16 * PITCHB) + ko);
            }
            // non-trans B reg order: r0=(n0-7,k0-7) r1=(n8-15,k0-7) r2=(n0-7,k8-15) r3=(n8-15,k8-15)
#pragma unroll
            for (int mi = 0; mi < 4; mi++)
#pragma unroll
                for (int nj = 0; nj < 8; nj++)
                    mma16816(acc[mi][nj], af[cur][mi],
                             bf[cur][nj >> 1][nj & 1], bf[cur][nj >> 1][(nj & 1) + 2]);
        }
    }

    // ---- epilogue: scale + fp32 stores ----
    const int gr = lane >> 2, cq = lane & 3;
    const size_t row0 = (size_t)bm * 128 + wm * 64 + gr;
    const int col0 = bn * 128 + wn * 64 + cq * 2;
#pragma unroll
    for (int mi = 0; mi < 4; mi++) {
#pragma unroll
        for (int nj = 0; nj < 8; nj++) {
            float2 v0 = make_float2(acc[mi][nj][0] * SCALE_F, acc[mi][nj][1] * SCALE_F);
            float2 v1 = make_float2(acc[mi][nj][2] * SCALE_F, acc[mi][nj][3] * SCALE_F);
            *(float2*)(out + (row0 + mi * 16) * T_DIM + col0 + nj * 8) = v0;
            *(float2*)(out + (row0 + mi * 16 + 8) * T_DIM + col0 + nj * 8) = v1;
        }
    }
#undef LOAD_STAGE
}

extern "C" void kernel_launch(void* const* d_in, const int* in_sizes, int n_in,
                              void* d_out, int out_size) {
    const float* nt = (const float*)d_in[0];  // neurotransmitters (256, 8192)
    const float* ap = (const float*)d_in[2];  // action_potential  (256, 8192)
    float* out = (float*)d_out;               // (8192, 8192) fp32

    // pass 1: fp32 -> fp16 with transpose to [s][k] / [t][k]
    cvt_t_kernel<<<dim3(S_DIM / 64, K_DIM / 64, 2), 256>>>(nt, ap);

    // pass 2: tensor-core GEMM, non-trans ldmatrix operand path
    cudaFuncSetAttribute(stdp_gemm_kernel,
                         cudaFuncAttributeMaxDynamicSharedMemorySize, SMEM_BYTES);
    dim3 grid(S_DIM / 128, T_DIM / 128);  // (64, 64)
    stdp_gemm_kernel<<<grid, THREADS, SMEM_BYTES>>>(out);
}